// round 10
// baseline (speedup 1.0000x reference)
#include <cuda_runtime.h>
#include <cstdint>

// CRF forward partition function, linear-domain reformulation, R10.
// R10 = fused-2 batches per warp + balanced 36-FFMA2 matvec.
//  * 2 independent batches per warp (E regs shared): the two scan chains
//    interleave in one instruction stream -> RAW latency hidden.
//  * Balanced rows: lane L does row L fully (24 FFMA2) + HALF of row
//    32+(L&15) (12 FFMA2); halves combined via one shfl_xor(16)+add.
//  * p stored twice (normal + rotated by 24 floats); lanes>=16 read the
//    rotated copy with setup-permuted E order -> all register indices
//    uniform, no divergent selects, half-loads reuse pv[0..5].
// Numerics: per-step exact power-of-2 renorm with one-step lag, analytic
// PAD chain, cp.async 16-step double-buffered feed (per batch).

#define KK 48
#define TT 1024
#define BB 512
#define CH 16
#define NCHUNK (TT / CH)
#define PAD_TAG 45
#define STOP_TAG 47
#define NEGV (-10000.0f)
#define LOG2E 1.4426950408889634f
#define LN2F 0.6931471805599453f

typedef unsigned long long ull;

__device__ __forceinline__ float ex2(float x) {
    float r; asm("ex2.approx.f32 %0, %1;" : "=f"(r) : "f"(x)); return r;
}
__device__ __forceinline__ float lg2(float x) {
    float r; asm("lg2.approx.f32 %0, %1;" : "=f"(r) : "f"(x)); return r;
}
__device__ __forceinline__ ull pk2(float lo, float hi) {
    ull r;
    asm("mov.b64 %0, {%1, %2};" : "=l"(r) : "f"(lo), "f"(hi));
    return r;
}
__device__ __forceinline__ void upk2(float& lo, float& hi, ull v) {
    asm("mov.b64 {%0, %1}, %2;" : "=f"(lo), "=f"(hi) : "l"(v));
}
__device__ __forceinline__ void ffma2(ull& acc, ull a, ull b) {
    asm("fma.rn.f32x2 %0, %1, %2, %0;" : "+l"(acc) : "l"(a), "l"(b));
}
__device__ __forceinline__ ull add2(ull a, ull b) {
    ull r;
    asm("add.rn.f32x2 %0, %1, %2;" : "=l"(r) : "l"(a), "l"(b));
    return r;
}
__device__ __forceinline__ void cpasync16(uint32_t saddr, const void* gaddr) {
    asm volatile("cp.async.cg.shared.global [%0], [%1], 16;"
                 :: "r"(saddr), "l"(gaddr));
}
__device__ __forceinline__ void cpcommit() {
    asm volatile("cp.async.commit_group;");
}
__device__ __forceinline__ void cpwait1() {
    asm volatile("cp.async.wait_group 1;");
}

__global__ __launch_bounds__(64, 1)
void crf_fwd_kernel(const float* __restrict__ h_tag,
                    const float* __restrict__ mask,
                    const float* __restrict__ trans,
                    float* __restrict__ out) {
    __shared__ __align__(16) float trs[KK * KK];
    __shared__ __align__(16) float pdm[2][2][2][KK];       // [warp][batch][copy]
    __shared__ __align__(16) float sm_em[2][2][2][CH * KK];// [warp][batch][buf]
    __shared__ __align__(16) float sm_mk[2][2][2][CH];

    const int tid  = threadIdx.x;
    const int wid  = tid >> 5;          // 0..1
    const int lane = tid & 31;
    const int bA   = (blockIdx.x * 2 + wid) * 2;
    const int bB   = bA + 1;

    const float* embA = h_tag + (size_t)bA * TT * KK;
    const float* embB = h_tag + (size_t)bB * TT * KK;
    const float* mkbA = mask + (size_t)bA * TT;
    const float* mkbB = mask + (size_t)bB * TT;

    // ---- cp.async chunk feed: both batches, one commit per chunk ----
    auto issue_chunk = [&](int cc) {
        const int buf = cc & 1;
#pragma unroll
        for (int ba = 0; ba < 2; ++ba) {
            const float* src = (ba ? embB : embA) + cc * (CH * KK);
            uint32_t dst =
                (uint32_t)__cvta_generic_to_shared(&sm_em[wid][ba][buf][0]);
#pragma unroll
            for (int it = 0; it < (CH * KK) / (32 * 4); ++it) {   // 6 iters
                int off = (it * 32 + lane) * 4;
                cpasync16(dst + (uint32_t)off * 4u, src + off);
            }
            if (lane < CH / 4) {
                uint32_t md =
                    (uint32_t)__cvta_generic_to_shared(&sm_mk[wid][ba][buf][0]);
                cpasync16(md + (uint32_t)lane * 16u,
                          (ba ? mkbB : mkbA) + cc * CH + lane * 4);
            }
        }
        cpcommit();
    };
    issue_chunk(0);
    issue_chunk(1);

    for (int i = tid; i < KK * KK; i += 64) trs[i] = trans[i];
    __syncthreads();

    const int  i1   = lane;                     // own row 0..31
    const bool has2 = (lane < 16);
    const int  i2   = has2 ? (lane + 32) : 0;   // clamped for safe loads
    const int  hrow = 32 + (lane & 15);         // half-row 32..47
    const int  rot1 = (lane < 24) ? (lane + 24) : (lane - 24);
    const int  rot2 = lane + 8;                 // (i2+24)%48, lanes<16

    // E own row (row i1, all 48 j as 24 pairs), j-pair order PERMUTED for
    // lanes>=16 to match the rotated p copy (pair m <-> pair (m+12)%24).
    // Columns 45 (PAD) and 47 (STOP) forced to exact zero.
    ull EpOwn[24];
    float rs1 = 0.f;
#pragma unroll
    for (int m = 0; m < 24; ++m) {
        const int pm = (lane < 16) ? m : ((m + 12) % 24);
        const int j0 = 2 * pm, j1 = j0 + 1;
        const bool z1 = (j1 == PAD_TAG) || (j1 == STOP_TAG);
        float e0 = ex2(trs[i1 * KK + j0] * LOG2E);
        float e1 = z1 ? 0.f : ex2(trs[i1 * KK + j1] * LOG2E);
        EpOwn[m] = pk2(e0, e1);
        rs1 += e0 + e1;
    }
    // E half row: row hrow, 24 j's (low half for lanes<16, high for >=16).
    ull EpHalf[12];
#pragma unroll
    for (int m = 0; m < 12; ++m) {
        const int j0 = ((lane < 16) ? 0 : 24) + 2 * m;
        const int j1 = j0 + 1;
        const bool z1 = (j1 == PAD_TAG) || (j1 == STOP_TAG);
        float e0 = ex2(trs[hrow * KK + j0] * LOG2E);
        float e1 = z1 ? 0.f : ex2(trs[hrow * KK + j1] * LOG2E);
        EpHalf[m] = pk2(e0, e1);
    }
    // Full rowsum of row i2 (init only; lanes<16).
    float rs2 = 0.f;
    if (has2) {
#pragma unroll
        for (int j = 0; j < KK; ++j) {
            if (j == PAD_TAG || j == STOP_TAG) continue;
            rs2 += ex2(trs[i2 * KK + j] * LOG2E);
        }
    }
    const float ES1 = ex2(trs[STOP_TAG * KK + i1] * LOG2E);
    const float ES2 = has2 ? ex2(trs[STOP_TAG * KK + i2] * LOG2E) : 0.f;

    const float base1 = 1.f + rs1;                       // i1 never PAD
    const float base2 = ((i2 == PAD_TAG) ? 0.f : 1.f) + rs2;

    float* pdA  = pdm[wid][0][0];
    float* pdAr = pdm[wid][0][1];
    float* pdB  = pdm[wid][1][0];
    float* pdBr = pdm[wid][1][1];
    const ulonglong2* pbA = (const ulonglong2*)(has2 ? pdA : pdAr);
    const ulonglong2* pbB = (const ulonglong2*)(has2 ? pdB : pdBr);

    float p1A, p2A, padA, p1B, p2B, padB;
    int cA = 0, cB = 0, eprevA, eprevB;
    {
        float emA1 = embA[i1], emA2 = has2 ? embA[i2] : 0.f;
        float emB1 = embB[i1], emB2 = has2 ? embB[i2] : 0.f;
        p1A = ex2(emA1 * LOG2E) * base1;
        p2A = has2 ? (ex2(emA2 * LOG2E) * base2) : 0.f;
        p1B = ex2(emB1 * LOG2E) * base1;
        p2B = has2 ? (ex2(emB2 * LOG2E) * base2) : 0.f;
        padA = emA2; padB = emB2;       // lane 13: i2 == 45 == PAD

        pdA[i1] = p1A; pdAr[rot1] = p1A;
        pdB[i1] = p1B; pdBr[rot1] = p1B;
        if (has2) {
            pdA[i2] = p2A; pdAr[rot2] = p2A;
            pdB[i2] = p2B; pdBr[rot2] = p2B;
        }
        float zpA = __shfl_sync(0xffffffffu, p1A, 0);
        float zpB = __shfl_sync(0xffffffffu, p1B, 0);
        int ea = (__float_as_int(zpA) >> 23) & 255;
        int eb = (__float_as_int(zpB) >> 23) & 255;
        eprevA = (ea == 0) ? 0 : (ea - 127);
        eprevB = (eb == 0) ? 0 : (eb - 127);
    }

    // ---- fused step: both batches, balanced matvec ----
    auto step = [&](const float* __restrict__ eAb,
                    const float* __restrict__ eBb,
                    const float* __restrict__ mAb,
                    const float* __restrict__ mBb, int tt) {
        const float cemA1 = eAb[tt * KK + i1];
        const float cemA2 = eAb[tt * KK + i2];
        const float cemB1 = eBb[tt * KK + i1];
        const float cemB2 = eBb[tt * KK + i2];
        const bool  mA = (mAb[tt] != 0.0f);
        const bool  mB = (mBb[tt] != 0.0f);

        __syncwarp();   // prior stores -> this step's reloads

        const float neA = -(float)eprevA;
        const float neB = -(float)eprevB;
        const float gA1 = ex2(fmaf(cemA1, LOG2E, neA));
        const float gA2 = ex2(fmaf(cemA2, LOG2E, neA));
        const float gB1 = ex2(fmaf(cemB1, LOG2E, neB));
        const float gB2 = ex2(fmaf(cemB2, LOG2E, neB));

        // ---- batch A ----
        ulonglong2 pv[12];
#pragma unroll
        for (int k = 0; k < 12; ++k) pv[k] = pbA[k];

        ull a0 = 0ull, a1 = 0ull, a2 = 0ull, a3 = 0ull;
        ull h0 = 0ull, h1 = 0ull;
#pragma unroll
        for (int k = 0; k < 12; k += 2) {
            ffma2(a0, pv[k].x,     EpOwn[2 * k]);
            ffma2(a1, pv[k].y,     EpOwn[2 * k + 1]);
            ffma2(a2, pv[k + 1].x, EpOwn[2 * k + 2]);
            ffma2(a3, pv[k + 1].y, EpOwn[2 * k + 3]);
        }
#pragma unroll
        for (int k = 0; k < 6; ++k) {       // half row: reuse pv[0..5]
            ffma2(h0, pv[k].x, EpHalf[2 * k]);
            ffma2(h1, pv[k].y, EpHalf[2 * k + 1]);
        }
        {
            const ull qo = add2(add2(a0, a1), add2(a2, a3));
            const ull qh = add2(h0, h1);
            float olo, ohi, hlo, hhi;
            upk2(olo, ohi, qo);
            upk2(hlo, hhi, qh);
            const float qown  = olo + ohi;
            float qhalf = hlo + hhi;
            qhalf += __shfl_xor_sync(0xffffffffu, qhalf, 16);
            p1A = mA ? (qown * gA1)  : p1A;
            p2A = mA ? (qhalf * gA2) : p2A;
        }
        padA += mA ? cemA2 : 0.f;
        cA   += mA ? eprevA : 0;

        // ---- batch B ----
#pragma unroll
        for (int k = 0; k < 12; ++k) pv[k] = pbB[k];

        ull b0 = 0ull, b1 = 0ull, b2 = 0ull, b3 = 0ull;
        ull g0 = 0ull, g1_ = 0ull;
#pragma unroll
        for (int k = 0; k < 12; k += 2) {
            ffma2(b0, pv[k].x,     EpOwn[2 * k]);
            ffma2(b1, pv[k].y,     EpOwn[2 * k + 1]);
            ffma2(b2, pv[k + 1].x, EpOwn[2 * k + 2]);
            ffma2(b3, pv[k + 1].y, EpOwn[2 * k + 3]);
        }
#pragma unroll
        for (int k = 0; k < 6; ++k) {
            ffma2(g0, pv[k].x, EpHalf[2 * k]);
            ffma2(g1_, pv[k].y, EpHalf[2 * k + 1]);
        }
        {
            const ull qo = add2(add2(b0, b1), add2(b2, b3));
            const ull qh = add2(g0, g1_);
            float olo, ohi, hlo, hhi;
            upk2(olo, ohi, qo);
            upk2(hlo, hhi, qh);
            const float qown  = olo + ohi;
            float qhalf = hlo + hhi;
            qhalf += __shfl_xor_sync(0xffffffffu, qhalf, 16);
            p1B = mB ? (qown * gB1)  : p1B;
            p2B = mB ? (qhalf * gB2) : p2B;
        }
        padB += mB ? cemB2 : 0.f;
        cB   += mB ? eprevB : 0;

        // lagged exponent proxies
        const float zpA = __shfl_sync(0xffffffffu, p1A, 0);
        const float zpB = __shfl_sync(0xffffffffu, p1B, 0);

        // stores: both copies, both batches (guarded by next step's sync)
        pdA[i1] = p1A; pdAr[rot1] = p1A;
        pdB[i1] = p1B; pdBr[rot1] = p1B;
        if (has2) {
            pdA[i2] = p2A; pdAr[rot2] = p2A;
            pdB[i2] = p2B; pdBr[rot2] = p2B;
        }

        const int ea = (__float_as_int(zpA) >> 23) & 255;
        const int eb = (__float_as_int(zpB) >> 23) & 255;
        eprevA = (ea == 0) ? 0 : (ea - 127);
        eprevB = (eb == 0) ? 0 : (eb - 127);
    };

    // ---- chunk 0 (steps 1..15) ----
    {
        cpwait1();
        __syncwarp();
        const float* eA = sm_em[wid][0][0];
        const float* eB = sm_em[wid][1][0];
        const float* mA_ = sm_mk[wid][0][0];
        const float* mB_ = sm_mk[wid][1][0];
#pragma unroll 1
        for (int tt = 1; tt < CH; ++tt) step(eA, eB, mA_, mB_, tt);
        issue_chunk(2);
    }

    // ---- chunks 1..63 ----
#pragma unroll 1
    for (int cc = 1; cc < NCHUNK; ++cc) {
        cpwait1();
        __syncwarp();
        const int buf = cc & 1;
        const float* eA = sm_em[wid][0][buf];
        const float* eB = sm_em[wid][1][buf];
        const float* mA_ = sm_mk[wid][0][buf];
        const float* mB_ = sm_mk[wid][1][buf];
#pragma unroll 1
        for (int tt = 0; tt < CH; ++tt) step(eA, eB, mA_, mB_, tt);
        if (cc + 2 < NCHUNK) issue_chunk(cc + 2);
    }

    // ---- finals ----
    float sA = p1A * ES1 + (has2 ? p2A * ES2 : 0.f);
    float sB = p1B * ES1 + (has2 ? p2B * ES2 : 0.f);
#pragma unroll
    for (int o = 16; o > 0; o >>= 1) {
        sA += __shfl_xor_sync(0xffffffffu, sA, o);
        sB += __shfl_xor_sync(0xffffffffu, sB, o);
    }
    const float CA    = NEGV * LOG2E + (float)cA;
    const float CB    = NEGV * LOG2E + (float)cB;
    const float mainA = CA + lg2(sA);
    const float mainB = CB + lg2(sB);
    const float padvA = __shfl_sync(0xffffffffu, padA, 13);
    const float padvB = __shfl_sync(0xffffffffu, padB, 13);
    const float padA2 = (padvA + NEGV) * LOG2E;
    const float padB2 = (padvB + NEGV) * LOG2E;

    if (lane == 0) {
        float hi = fmaxf(mainA, padA2), lo = fminf(mainA, padA2);
        out[bA] = (hi + lg2(1.0f + ex2(lo - hi))) * LN2F;
        hi = fmaxf(mainB, padB2); lo = fminf(mainB, padB2);
        out[bB] = (hi + lg2(1.0f + ex2(lo - hi))) * LN2F;
    }
}

extern "C" void kernel_launch(void* const* d_in, const int* in_sizes, int n_in,
                              void* d_out, int out_size) {
    const float* h_tag = (const float*)d_in[0];
    const float* mask  = (const float*)d_in[1];
    const float* trans = (const float*)d_in[2];
    float* out = (float*)d_out;
    (void)in_sizes; (void)n_in; (void)out_size;
    crf_fwd_kernel<<<BB / 4, 64>>>(h_tag, mask, trans, out);
}

// round 11
// speedup vs baseline: 1.4883x; 1.4883x over previous
#include <cuda_runtime.h>
#include <cstdint>

// CRF forward partition function, linear-domain reformulation, R11.
// Base = R9 (best: 135.7us). R11 removes per-step warp synchronization:
// the step body is fully convergent (branchless, uniform bounds), so the
// STS -> LDS cross-lane round trip is ordered by the per-warp in-order LSU;
// only COMPILER reordering must be prevented -> zero-instruction
// asm-memory fences replace the two per-step __syncwarp (23 cyc each,
// B300-measured). Real __syncwarp remains at the 64 chunk boundaries for
// cp.async visibility. Step also reordered: 12 pv LDS.128 issued first
// (longest pole), then emissions, then MUFU.
// Numerics unchanged: j-packed matvec, per-step exact power-of-2 renorm
// with one-step lag, analytic PAD chain, cp.async double-buffered feed.

#define KK 48
#define TT 1024
#define BB 512
#define CH 16
#define NCHUNK (TT / CH)
#define PAD_TAG 45
#define STOP_TAG 47
#define NEGV (-10000.0f)
#define LOG2E 1.4426950408889634f
#define LN2F 0.6931471805599453f

typedef unsigned long long ull;

__device__ __forceinline__ float ex2(float x) {
    float r; asm("ex2.approx.f32 %0, %1;" : "=f"(r) : "f"(x)); return r;
}
__device__ __forceinline__ float lg2(float x) {
    float r; asm("lg2.approx.f32 %0, %1;" : "=f"(r) : "f"(x)); return r;
}
__device__ __forceinline__ ull pk2(float lo, float hi) {
    ull r;
    asm("mov.b64 %0, {%1, %2};" : "=l"(r) : "f"(lo), "f"(hi));
    return r;
}
__device__ __forceinline__ void upk2(float& lo, float& hi, ull v) {
    asm("mov.b64 {%0, %1}, %2;" : "=f"(lo), "=f"(hi) : "l"(v));
}
__device__ __forceinline__ void ffma2(ull& acc, ull a, ull b) {
    asm("fma.rn.f32x2 %0, %1, %2, %0;" : "+l"(acc) : "l"(a), "l"(b));
}
__device__ __forceinline__ ull add2(ull a, ull b) {
    ull r;
    asm("add.rn.f32x2 %0, %1, %2;" : "=l"(r) : "l"(a), "l"(b));
    return r;
}
__device__ __forceinline__ void cfence() {            // compiler-only fence
    asm volatile("" ::: "memory");
}
__device__ __forceinline__ void cpasync16(uint32_t saddr, const void* gaddr) {
    asm volatile("cp.async.cg.shared.global [%0], [%1], 16;"
                 :: "r"(saddr), "l"(gaddr));
}
__device__ __forceinline__ void cpcommit() {
    asm volatile("cp.async.commit_group;");
}
__device__ __forceinline__ void cpwait1() {
    asm volatile("cp.async.wait_group 1;");
}

__global__ __launch_bounds__(128, 1)
void crf_fwd_kernel(const float* __restrict__ h_tag,
                    const float* __restrict__ mask,
                    const float* __restrict__ trans,
                    float* __restrict__ out) {
    __shared__ __align__(16) float trs[KK * KK];
    __shared__ __align__(16) float pd[4][KK];              // UNduplicated p
    __shared__ __align__(16) float sm_em[4][2][CH * KK];   // emission chunks
    __shared__ __align__(16) float sm_mk[4][2][CH];        // mask chunks

    const int tid  = threadIdx.x;
    const int wid  = tid >> 5;
    const int lane = tid & 31;
    const int b    = blockIdx.x * 4 + wid;

    const float* emb = h_tag + (size_t)b * TT * KK;
    const float* mkb = mask + (size_t)b * TT;

    // ---- deep prefetch: issue chunks 0 and 1 immediately ----
    auto issue_chunk = [&](int cc) {
        const float* src = emb + cc * (CH * KK);
        uint32_t dst = (uint32_t)__cvta_generic_to_shared(&sm_em[wid][cc & 1][0]);
#pragma unroll
        for (int it = 0; it < (CH * KK) / (32 * 4); ++it) {   // 6 iters
            int off = (it * 32 + lane) * 4;                   // float index
            cpasync16(dst + (uint32_t)off * 4u, src + off);
        }
        if (lane < CH / 4) {
            uint32_t md = (uint32_t)__cvta_generic_to_shared(&sm_mk[wid][cc & 1][0]);
            cpasync16(md + (uint32_t)lane * 16u, mkb + cc * CH + lane * 4);
        }
        cpcommit();
    };
    issue_chunk(0);
    issue_chunk(1);

    // Stage trans coalesced into shared (overlaps cp.async flight).
    for (int i = tid; i < KK * KK; i += 128) trs[i] = trans[i];
    __syncthreads();

    const int  i1   = lane;
    const bool has2 = (lane < 16);
    const int  i2   = has2 ? (lane + 32) : 0;   // clamped for safe loads

    // E rows, j-packed: EpA[m] = pack(E[i1][2m], E[i1][2m+1]) etc.
    // Columns 45 (PAD) and 47 (STOP) forced to exact 0.
    ull EpA[24], EpB[24];
    float rs1 = 0.f, rs2 = 0.f;
#pragma unroll
    for (int m = 0; m < 24; ++m) {
        const int j0 = 2 * m;          // even: never 45/47
        const int j1 = 2 * m + 1;      // odd: may be 45 or 47
        const bool z1 = (j1 == PAD_TAG) || (j1 == STOP_TAG);
        float eA0 = ex2(trs[i1 * KK + j0] * LOG2E);
        float eA1 = z1 ? 0.f : ex2(trs[i1 * KK + j1] * LOG2E);
        float eB0 = has2 ? ex2(trs[i2 * KK + j0] * LOG2E) : 0.f;
        float eB1 = (has2 && !z1) ? ex2(trs[i2 * KK + j1] * LOG2E) : 0.f;
        EpA[m] = pk2(eA0, eA1);
        EpB[m] = pk2(eB0, eB1);
        rs1 += eA0 + eA1;
        rs2 += eB0 + eB1;
    }
    const float ES1 = ex2(trs[STOP_TAG * KK + i1] * LOG2E);
    const float ES2 = has2 ? ex2(trs[STOP_TAG * KK + i2] * LOG2E) : 0.f;

    // Exact init at group scale C0 = NEG*log2e:
    // p_i(1) = g_i * ( [i != PAD] + sum_{j not in {PAD,STOP}} E[i][j] )
    const float base1 = ((i1 == PAD_TAG) ? 0.f : 1.f) + rs1;
    const float base2 = ((has2 && i2 == PAD_TAG) ? 0.f : 1.f) + rs2;

    float* pdw = pd[wid];

    float p1, p2, padacc;
    int c = 0, eprev;
    {
        float em1 = emb[i1];
        float em2 = has2 ? emb[i2] : 0.f;
        p1 = ex2(em1 * LOG2E) * base1;
        p2 = has2 ? (ex2(em2 * LOG2E) * base2) : 0.f;
        padacc = em2;   // lane 13 (i2 == 45 == PAD) is the meaningful one

        pdw[i1] = p1;
        if (has2) pdw[i2] = p2;
        float zp = __shfl_sync(0xffffffffu, p1, 0);
        int eb = (__float_as_int(zp) >> 23) & 255;
        eprev = (eb == 0) ? 0 : (eb - 127);
        __syncwarp();   // one real sync before the scan starts
    }

    // ---- scan step: pv loads first (longest pole), compiler fences only.
    //      Convergent warp => STS->LDS ordered by in-order per-warp LSU.
    auto step = [&](const float* __restrict__ embuf,
                    const float* __restrict__ mkbuf, int tt) {
        // 1) fence: prior stores may not sink below; loads may not hoist above
        cfence();

        // 2) batched p-vector load: 48 floats = 12 x LDS.128, max MLP
        ulonglong2 pv[12];
        const ulonglong2* pdv = (const ulonglong2*)pdw;
#pragma unroll
        for (int k = 0; k < 12; ++k) pv[k] = pdv[k];

        // 3) this step's emissions/mask (independent of pd)
        const float cem1 = embuf[tt * KK + i1];
        const float cem2 = embuf[tt * KK + i2];
        const float cmk  = mkbuf[tt];

        // 4) growth factors (MUFU hides under the load flight)
        const bool  m  = (cmk != 0.0f);
        const float ne = -(float)eprev;
        const float g1 = ex2(fmaf(cem1, LOG2E, ne));
        const float g2 = ex2(fmaf(cem2, LOG2E, ne));

        // 5) j-packed matvec: 8 independent FFMA2 chains, 6 deep
        ull a0 = 0ull, a1 = 0ull, a2 = 0ull, a3 = 0ull;
        ull b0 = 0ull, b1 = 0ull, b2 = 0ull, b3 = 0ull;
#pragma unroll
        for (int k = 0; k < 12; k += 2) {
            ffma2(a0, pv[k].x,     EpA[2 * k]);
            ffma2(a1, pv[k].y,     EpA[2 * k + 1]);
            ffma2(a2, pv[k + 1].x, EpA[2 * k + 2]);
            ffma2(a3, pv[k + 1].y, EpA[2 * k + 3]);
            ffma2(b0, pv[k].x,     EpB[2 * k]);
            ffma2(b1, pv[k].y,     EpB[2 * k + 1]);
            ffma2(b2, pv[k + 1].x, EpB[2 * k + 2]);
            ffma2(b3, pv[k + 1].y, EpB[2 * k + 3]);
        }
        const ull qA = add2(add2(a0, a1), add2(a2, a3));
        const ull qB = add2(add2(b0, b1), add2(b2, b3));
        float qalo, qahi, qblo, qbhi;
        upk2(qalo, qahi, qA);
        upk2(qblo, qbhi, qB);
        const float q1 = (qalo + qahi) * g1;   // horizontal add + scale
        const float q2 = (qblo + qbhi) * g2;

        p1 = m ? q1 : p1;
        p2 = m ? q2 : p2;
        padacc += m ? cem2 : 0.f;
        c      += m ? eprev : 0;

        // 6) lagged exponent proxy (consumed next step; latency hidden)
        const float zp = __shfl_sync(0xffffffffu, p1, 0);

        // 7) store new p (fence at next step's top orders vs its loads)
        pdw[i1] = p1;
        if (has2) pdw[i2] = p2;
        cfence();

        const int eb2 = (__float_as_int(zp) >> 23) & 255;
        eprev = (eb2 == 0) ? 0 : (eb2 - 127);
    };

    // ---- chunk 0 (steps 1..15; step 0 handled by init) ----
    {
        cpwait1();        // group 0 complete (only group 1 may remain pending)
        __syncwarp();     // publish chunk 0 across lanes (real sync, 1/16 steps)
        const float* embuf = sm_em[wid][0];
        const float* mkbuf = sm_mk[wid][0];
#pragma unroll 2
        for (int tt = 1; tt < CH; ++tt) step(embuf, mkbuf, tt);
        issue_chunk(2);
    }

    // ---- chunks 1..63 ----
#pragma unroll 1
    for (int cc = 1; cc < NCHUNK; ++cc) {
        cpwait1();        // chunk cc resident (only cc+1 may remain pending)
        __syncwarp();     // publish chunk cc across lanes
        const int buf = cc & 1;
        const float* embuf = sm_em[wid][buf];
        const float* mkbuf = sm_mk[wid][buf];
#pragma unroll 2
        for (int tt = 0; tt < CH; ++tt) step(embuf, mkbuf, tt);
        if (cc + 2 < NCHUNK) issue_chunk(cc + 2);
    }

    // ---- final: lse_j(score_j + trans[STOP][j]) at scale C, merged with
    //      the analytic PAD chain (+ trans[STOP][PAD] = NEG). ----
    float s = p1 * ES1 + (has2 ? p2 * ES2 : 0.f);
#pragma unroll
    for (int o = 16; o > 0; o >>= 1)
        s += __shfl_xor_sync(0xffffffffu, s, o);

    const float C     = NEGV * LOG2E + (float)c;
    const float main2 = C + lg2(s);
    const float padv  = __shfl_sync(0xffffffffu, padacc, 13);
    const float pad2  = (padv + NEGV) * LOG2E;
    const float hi = fmaxf(main2, pad2);
    const float lo = fminf(main2, pad2);
    const float ans2 = hi + lg2(1.0f + ex2(lo - hi));

    if (lane == 0) out[b] = ans2 * LN2F;
}

extern "C" void kernel_launch(void* const* d_in, const int* in_sizes, int n_in,
                              void* d_out, int out_size) {
    const float* h_tag = (const float*)d_in[0];
    const float* mask  = (const float*)d_in[1];
    const float* trans = (const float*)d_in[2];
    float* out = (float*)d_out;
    (void)in_sizes; (void)n_in; (void)out_size;
    crf_fwd_kernel<<<BB / 4, 128>>>(h_tag, mask, trans, out);
}

// round 13
// speedup vs baseline: 1.6447x; 1.1051x over previous
#include <cuda_runtime.h>
#include <cstdint>

// CRF forward partition function, linear-domain, R12: forward-backward split.
// Z = w^T (Prod_t M_t) p0 split at t=511: warp pair per batch computes
// alpha(511) forward (511 matvecs) and beta(511) backward (512 matvecs,
// E^T in regs), combined once at the end: Z = sum_i alpha_i beta_i.
// -> 1024 independent warps = 2 per SMSP on 128 SMs; each warp does half
// the sequential steps; SMSP issue ports near-saturated.
// Backward: r_t = g_t (x) beta(t) stored (one-step shift so the store sits
// at the step tail like forward); beta(t-1) = E^T r_t; mask_t selects;
// escale carries the renorm exponent embedded in the stored r.
// PAD/STOP rows stay exactly 0 backward via ex2 underflow (no forcing).
// Per-warp numerics as R9/R11: j-packed matvec, exact power-of-2 renorm
// with one-step lag, analytic PAD chain, cp.async CH=8 double-buffered.

#define KK 48
#define TT 1024
#define BB 512
#define CH 8
#define NCHUNK (TT / CH)        // 128
#define FWD_CHUNKS 64           // forward: chunks 0..63  (t = 1..511)
#define PAD_TAG 45
#define STOP_TAG 47
#define NEGV (-10000.0f)
#define LOG2E 1.4426950408889634f
#define LN2F 0.6931471805599453f

typedef unsigned long long ull;

__device__ __forceinline__ float ex2(float x) {
    float r; asm("ex2.approx.f32 %0, %1;" : "=f"(r) : "f"(x)); return r;
}
__device__ __forceinline__ float lg2(float x) {
    float r; asm("lg2.approx.f32 %0, %1;" : "=f"(r) : "f"(x)); return r;
}
__device__ __forceinline__ ull pk2(float lo, float hi) {
    ull r;
    asm("mov.b64 %0, {%1, %2};" : "=l"(r) : "f"(lo), "f"(hi));
    return r;
}
__device__ __forceinline__ void upk2(float& lo, float& hi, ull v) {
    asm("mov.b64 {%0, %1}, %2;" : "=f"(lo), "=f"(hi) : "l"(v));
}
__device__ __forceinline__ void ffma2(ull& acc, ull a, ull b) {
    asm("fma.rn.f32x2 %0, %1, %2, %0;" : "+l"(acc) : "l"(a), "l"(b));
}
__device__ __forceinline__ ull add2(ull a, ull b) {
    ull r;
    asm("add.rn.f32x2 %0, %1, %2;" : "=l"(r) : "l"(a), "l"(b));
    return r;
}
__device__ __forceinline__ void cfence() { asm volatile("" ::: "memory"); }
__device__ __forceinline__ void cpasync16(uint32_t saddr, const void* gaddr) {
    asm volatile("cp.async.cg.shared.global [%0], [%1], 16;"
                 :: "r"(saddr), "l"(gaddr));
}
__device__ __forceinline__ void cpcommit() {
    asm volatile("cp.async.commit_group;");
}
__device__ __forceinline__ void cpwait1() {
    asm volatile("cp.async.wait_group 1;");
}
__device__ __forceinline__ int expof(float v) {
    int eb = (__float_as_int(v) >> 23) & 255;
    return (eb == 0) ? 0 : (eb - 127);
}

__global__ __launch_bounds__(256, 1)
void crf_fwd_kernel(const float* __restrict__ h_tag,
                    const float* __restrict__ mask,
                    const float* __restrict__ trans,
                    float* __restrict__ out) {
    __shared__ __align__(16) float pd[8][KK];              // per-warp operand vec
    __shared__ __align__(16) float sm_em[8][2][CH * KK];   // per-warp chunks
    __shared__ __align__(16) float sm_mk[8][2][CH];
    __shared__ __align__(16) float bd[4][KK];              // beta(511) exchange
    __shared__ float bsc_c[4];
    __shared__ float bsc_pad[4];

    const int tid   = threadIdx.x;
    const int wid   = tid >> 5;          // 0..7
    const int lane  = tid & 31;
    const int team  = wid & 3;
    const bool isF  = (wid < 4);
    const int b     = blockIdx.x * 4 + team;

    const float* emb = h_tag + (size_t)b * TT * KK;
    const float* mkb = mask + (size_t)b * TT;

    // ---- per-warp cp.async chunk feed. Backward emission window is
    //      shifted by -1 row (iteration t consumes em[t-1], mask[t]).
    auto issue_chunk = [&](int cc) {
        const int buf = cc & 1;
        const float* src = emb + (cc * CH - (isF ? 0 : 1)) * KK;
        uint32_t dst = (uint32_t)__cvta_generic_to_shared(&sm_em[wid][buf][0]);
#pragma unroll
        for (int it = 0; it < (CH * KK) / (32 * 4); ++it) {   // 3 iters
            int off = (it * 32 + lane) * 4;
            cpasync16(dst + (uint32_t)off * 4u, src + off);
        }
        if (lane < CH / 4) {                                  // 2 lanes
            uint32_t md = (uint32_t)__cvta_generic_to_shared(&sm_mk[wid][buf][0]);
            cpasync16(md + (uint32_t)lane * 16u, mkb + cc * CH + lane * 4);
        }
        cpcommit();
    };
    if (isF) { issue_chunk(0);          issue_chunk(1); }
    else     { issue_chunk(NCHUNK - 1); issue_chunk(NCHUNK - 2); }

    const int  i1   = lane;
    const bool has2 = (lane < 16);
    const int  i2   = has2 ? (lane + 32) : 0;   // clamped for safe loads

    // E (forward) or E^T (backward) rows, j-packed, from GLOBAL trans
    // (setup-only; L1/L2 resident after first touch). Forward zeroes
    // columns 45/47 exactly; backward needs no forcing (operand slots
    // 45/47 carry exact-zero r).
    ull EpA[24], EpB[24];
    float rs1 = 0.f, rs2 = 0.f;
#pragma unroll
    for (int m = 0; m < 24; ++m) {
        const int j0 = 2 * m, j1 = 2 * m + 1;
        const bool z1 = isF && ((j1 == PAD_TAG) || (j1 == STOP_TAG));
        const int a00 = isF ? (i1 * KK + j0) : (j0 * KK + i1);
        const int a01 = isF ? (i1 * KK + j1) : (j1 * KK + i1);
        const int a10 = isF ? (i2 * KK + j0) : (j0 * KK + i2);
        const int a11 = isF ? (i2 * KK + j1) : (j1 * KK + i2);
        float eA0 = ex2(trans[a00] * LOG2E);
        float eA1 = z1 ? 0.f : ex2(trans[a01] * LOG2E);
        float eB0 = has2 ? ex2(trans[a10] * LOG2E) : 0.f;
        float eB1 = (has2 && !z1) ? ex2(trans[a11] * LOG2E) : 0.f;
        EpA[m] = pk2(eA0, eA1);
        EpB[m] = pk2(eB0, eB1);
        rs1 += eA0 + eA1;
        rs2 += eB0 + eB1;
    }
    const float ES1 = ex2(trans[STOP_TAG * KK + i1] * LOG2E);
    const float ES2 = has2 ? ex2(trans[STOP_TAG * KK + i2] * LOG2E) : 0.f;

    float* pdw = pd[wid];

    // ---- state ----
    float p1, p2, padacc, pend = 0.f;
    int c = 0, eprev, escale = 0;
    if (isF) {
        // exact init at scale 2^(NEG*log2e): p(1)=g_1*([i!=PAD]+rowsum)
        const float base1 = ((i1 == PAD_TAG) ? 0.f : 1.f) + rs1;
        const float base2 = ((has2 && i2 == PAD_TAG) ? 0.f : 1.f) + rs2;
        float em1 = emb[i1];
        float em2 = has2 ? emb[i2] : 0.f;
        p1 = ex2(em1 * LOG2E) * base1;
        p2 = has2 ? (ex2(em2 * LOG2E) * base2) : 0.f;
        padacc = em2;                        // lane 13: i2 == PAD
        pdw[i1] = p1;
        if (has2) pdw[i2] = p2;
        eprev = expof(__shfl_sync(0xffffffffu, p1, 0));
    } else {
        // beta(1023) = w = exp(trans[STOP]); store r_1023 = g_1023 (*) w
        p1 = ES1;                            // beta regs
        p2 = ES2;
        padacc = 0.f;
        float em1 = emb[(size_t)(TT - 1) * KK + i1];
        float em2 = has2 ? emb[(size_t)(TT - 1) * KK + i2] : 0.f;
        pend = em2;                          // em[1023][PAD] pending
        eprev = expof(__shfl_sync(0xffffffffu, p1, 0));
        const float ne = -(float)eprev;
        pdw[i1] = p1 * ex2(fmaf(em1, LOG2E, ne));
        if (has2) pdw[i2] = p2 * ex2(fmaf(em2, LOG2E, ne));
        escale = eprev;
        eprev = expof(__shfl_sync(0xffffffffu, p1, 0));
    }
    __syncwarp();

    // ---- shared matvec core: q = M * pd (j-packed, 8 chains) ----
    auto matvec = [&](float& q1, float& q2) {
        ulonglong2 pv[12];
        const ulonglong2* pdv = (const ulonglong2*)pdw;
#pragma unroll
        for (int k = 0; k < 12; ++k) pv[k] = pdv[k];
        ull a0 = 0ull, a1 = 0ull, a2 = 0ull, a3 = 0ull;
        ull b0 = 0ull, b1 = 0ull, b2 = 0ull, b3 = 0ull;
#pragma unroll
        for (int k = 0; k < 12; k += 2) {
            ffma2(a0, pv[k].x,     EpA[2 * k]);
            ffma2(a1, pv[k].y,     EpA[2 * k + 1]);
            ffma2(a2, pv[k + 1].x, EpA[2 * k + 2]);
            ffma2(a3, pv[k + 1].y, EpA[2 * k + 3]);
            ffma2(b0, pv[k].x,     EpB[2 * k]);
            ffma2(b1, pv[k].y,     EpB[2 * k + 1]);
            ffma2(b2, pv[k + 1].x, EpB[2 * k + 2]);
            ffma2(b3, pv[k + 1].y, EpB[2 * k + 3]);
        }
        const ull qA = add2(add2(a0, a1), add2(a2, a3));
        const ull qB = add2(add2(b0, b1), add2(b2, b3));
        float qalo, qahi, qblo, qbhi;
        upk2(qalo, qahi, qA);
        upk2(qblo, qbhi, qB);
        q1 = qalo + qahi;
        q2 = qblo + qbhi;
    };

    if (isF) {
        // ================= FORWARD: t = 1..511 =================
        auto step = [&](const float* __restrict__ embuf,
                        const float* __restrict__ mkbuf, int tt) {
            const float cem1 = embuf[tt * KK + i1];
            const float cem2 = embuf[tt * KK + i2];
            const float cmk  = mkbuf[tt];
            cfence();
            float q1, q2;
            matvec(q1, q2);
            const bool  m  = (cmk != 0.0f);
            const float ne = -(float)eprev;
            const float g1 = ex2(fmaf(cem1, LOG2E, ne));
            const float g2 = ex2(fmaf(cem2, LOG2E, ne));
            p1 = m ? (q1 * g1) : p1;
            p2 = m ? (q2 * g2) : p2;
            padacc += m ? cem2 : 0.f;
            c      += m ? eprev : 0;
            const float zp = __shfl_sync(0xffffffffu, p1, 0);
            pdw[i1] = p1;
            if (has2) pdw[i2] = p2;
            cfence();
            eprev = expof(zp);
        };
        {   // chunk 0: t = 1..7
            cpwait1();
            __syncwarp();
#pragma unroll 1
            for (int tt = 1; tt < CH; ++tt)
                step(sm_em[wid][0], sm_mk[wid][0], tt);
            issue_chunk(2);
        }
#pragma unroll 1
        for (int cc = 1; cc < FWD_CHUNKS; ++cc) {
            cpwait1();
            __syncwarp();
            const int buf = cc & 1;
#pragma unroll 1
            for (int tt = 0; tt < CH; ++tt)
                step(sm_em[wid][buf], sm_mk[wid][buf], tt);
            if (cc + 2 < FWD_CHUNKS) issue_chunk(cc + 2);
        }
    } else {
        // ================= BACKWARD: t = 1023..512 =================
        // iteration t: beta(t-1) = E^T r_t (stored); select by mask[t];
        // then store r_{t-1} = g_{t-1} (*) beta  (em buffer is -1 shifted).
        auto bstep = [&](const float* __restrict__ embuf,
                         const float* __restrict__ mkbuf, int tt) {
            const float cem1 = embuf[tt * KK + i1];   // em[t-1]
            const float cem2 = embuf[tt * KK + i2];
            const float cmk  = mkbuf[tt];             // mask[t]
            cfence();
            float q1, q2;
            matvec(q1, q2);
            const bool m = (cmk != 0.0f);
            p1 = m ? q1 : p1;
            p2 = m ? q2 : p2;
            padacc += m ? pend : 0.f;
            c      += m ? escale : 0;
            pend = cem2;
            const float zp = __shfl_sync(0xffffffffu, p1, 0);
            const float ne = -(float)eprev;
            const float g1 = ex2(fmaf(cem1, LOG2E, ne));
            const float g2 = ex2(fmaf(cem2, LOG2E, ne));
            pdw[i1] = p1 * g1;
            if (has2) pdw[i2] = p2 * g2;
            cfence();
            escale = eprev;
            eprev = expof(zp);
        };
#pragma unroll 1
        for (int cc = NCHUNK - 1; cc >= FWD_CHUNKS; --cc) {
            cpwait1();
            __syncwarp();
            const int buf = cc & 1;
#pragma unroll 1
            for (int tt = CH - 1; tt >= 0; --tt)
                bstep(sm_em[wid][buf], sm_mk[wid][buf], tt);
            if (cc - 2 >= FWD_CHUNKS) issue_chunk(cc - 2);
        }
    }

    // ---- combine: Z_main = 2^(NEG*log2e + cF + cB) * sum_i alpha_i beta_i
    if (!isF) {
        bd[team][i1] = p1;
        if (has2) bd[team][i2] = p2;
        const float padv = __shfl_sync(0xffffffffu, padacc, 13);
        if (lane == 0) {
            bsc_c[team]   = (float)c;
            bsc_pad[team] = padv;
        }
    }
    __syncthreads();
    if (isF) {
        const float bt1 = bd[team][i1];
        const float bt2 = has2 ? bd[team][i2] : 0.f;
        float s = p1 * bt1 + p2 * bt2;
#pragma unroll
        for (int o = 16; o > 0; o >>= 1)
            s += __shfl_xor_sync(0xffffffffu, s, o);

        const float padF  = __shfl_sync(0xffffffffu, padacc, 13);
        const float Cfull = NEGV * LOG2E + (float)c + bsc_c[team];
        const float main2 = Cfull + lg2(s);
        const float pad2  = (padF + bsc_pad[team] + NEGV) * LOG2E;
        const float hi = fmaxf(main2, pad2);
        const float lo = fminf(main2, pad2);
        const float ans2 = hi + lg2(1.0f + ex2(lo - hi));
        if (lane == 0) out[b] = ans2 * LN2F;
    }
}

extern "C" void kernel_launch(void* const* d_in, const int* in_sizes, int n_in,
                              void* d_out, int out_size) {
    const float* h_tag = (const float*)d_in[0];
    const float* mask  = (const float*)d_in[1];
    const float* trans = (const float*)d_in[2];
    float* out = (float*)d_out;
    (void)in_sizes; (void)n_in; (void)out_size;
    crf_fwd_kernel<<<BB / 4, 256>>>(h_tag, mask, trans, out);
}

// round 15
// speedup vs baseline: 1.8538x; 1.1271x over previous
#include <cuda_runtime.h>
#include <cuda_bf16.h>
#include <cstdint>

// CRF forward, linear-domain, R15 = R12 (fwd/bwd split, 2 warps/SMSP)
// + bf16x2 matvec. R14 (fp16) failed on RANGE (cross-tag spread of p
// overflowed 2^15); bf16 keeps fp32's 8-bit exponent so ALL of R12's
// renorm logic (lane-0 proxy, power-of-2 ledger, analytic PAD chain)
// carries over unchanged. HFMA2.BF16_V2 is rt2/SMSP => 2x MAC rate vs
// fma.rn.f32x2 (measured rt~4 in R12's perfect 2-warp serialization).
// Precision guard: 8 accumulator chains only 6 products deep in bf16,
// one bf16 tree level, final combine in fp32.
// Structure otherwise identical to R12 (passed @ 1.32e-6, 124.8us).

#define KK 48
#define TT 1024
#define BB 512
#define CH 8
#define NCHUNK (TT / CH)        // 128
#define FWD_CHUNKS 64           // forward: chunks 0..63 (t = 1..511)
#define PAD_TAG 45
#define STOP_TAG 47
#define NEGV (-10000.0f)
#define LOG2E 1.4426950408889634f
#define LN2F 0.6931471805599453f

typedef uint32_t u32;

__device__ __forceinline__ float ex2(float x) {
    float r; asm("ex2.approx.f32 %0, %1;" : "=f"(r) : "f"(x)); return r;
}
__device__ __forceinline__ float lg2(float x) {
    float r; asm("lg2.approx.f32 %0, %1;" : "=f"(r) : "f"(x)); return r;
}
// pack two f32 -> bf16x2 (first PTX source lands in HIGH half)
__device__ __forceinline__ u32 f2bf2(float lo, float hi) {
    u32 r; asm("cvt.rn.bf16x2.f32 %0, %1, %2;" : "=r"(r) : "f"(hi), "f"(lo));
    return r;
}
// unpack bf16x2 -> two f32 (exact: bf16 is the top 16 bits of f32)
__device__ __forceinline__ void bf2f2(float& lo, float& hi, u32 h) {
    lo = __uint_as_float(h << 16);
    hi = __uint_as_float(h & 0xffff0000u);
}
__device__ __forceinline__ void bffma2(u32& d, u32 a, u32 b) {
    asm("fma.rn.bf16x2 %0, %1, %2, %0;" : "+r"(d) : "r"(a), "r"(b));
}
__device__ __forceinline__ u32 bfadd2(u32 a, u32 b) {
    u32 r; asm("add.rn.bf16x2 %0, %1, %2;" : "=r"(r) : "r"(a), "r"(b));
    return r;
}
__device__ __forceinline__ void cfence() { asm volatile("" ::: "memory"); }
__device__ __forceinline__ void cpasync16(u32 saddr, const void* gaddr) {
    asm volatile("cp.async.cg.shared.global [%0], [%1], 16;"
                 :: "r"(saddr), "l"(gaddr));
}
__device__ __forceinline__ void cpcommit() {
    asm volatile("cp.async.commit_group;");
}
__device__ __forceinline__ void cpwait1() {
    asm volatile("cp.async.wait_group 1;");
}
__device__ __forceinline__ int expof(float v) {
    int eb = (__float_as_int(v) >> 23) & 255;
    return (eb == 0) ? 0 : (eb - 127);
}

__global__ __launch_bounds__(256, 1)
void crf_fwd_kernel(const float* __restrict__ h_tag,
                    const float* __restrict__ mask,
                    const float* __restrict__ trans,
                    float* __restrict__ out) {
    __shared__ __align__(16) __nv_bfloat16 pdh[8][KK];     // bf16 operand vec
    __shared__ __align__(16) float sm_em[8][2][CH * KK];
    __shared__ __align__(16) float sm_mk[8][2][CH];
    __shared__ __align__(16) float bd[4][KK];              // beta exchange
    __shared__ float bsc_c[4];
    __shared__ float bsc_pad[4];

    const int tid   = threadIdx.x;
    const int wid   = tid >> 5;          // 0..7
    const int lane  = tid & 31;
    const int team  = wid & 3;
    const bool isF  = (wid < 4);
    const int b     = blockIdx.x * 4 + team;

    const float* emb = h_tag + (size_t)b * TT * KK;
    const float* mkb = mask + (size_t)b * TT;

    auto issue_chunk = [&](int cc) {
        const int buf = cc & 1;
        const float* src = emb + (cc * CH - (isF ? 0 : 1)) * KK;
        u32 dst = (u32)__cvta_generic_to_shared(&sm_em[wid][buf][0]);
#pragma unroll
        for (int it = 0; it < (CH * KK) / (32 * 4); ++it) {   // 3 iters
            int off = (it * 32 + lane) * 4;
            cpasync16(dst + (u32)off * 4u, src + off);
        }
        if (lane < CH / 4) {
            u32 md = (u32)__cvta_generic_to_shared(&sm_mk[wid][buf][0]);
            cpasync16(md + (u32)lane * 16u, mkb + cc * CH + lane * 4);
        }
        cpcommit();
    };
    if (isF) { issue_chunk(0);          issue_chunk(1); }
    else     { issue_chunk(NCHUNK - 1); issue_chunk(NCHUNK - 2); }

    const int  i1   = lane;
    const bool has2 = (lane < 16);
    const int  i2   = has2 ? (lane + 32) : 0;

    // E (fwd) or E^T (bwd) rows, j-packed bf16x2, from GLOBAL trans.
    // Forward zeroes columns 45/47 exactly; backward rows 45/47 of E^T
    // are exact 0 via ex2 underflow as in R12.
    u32 EhA[24], EhB[24];
    float rs1 = 0.f, rs2 = 0.f;
#pragma unroll
    for (int m = 0; m < 24; ++m) {
        const int j0 = 2 * m, j1 = 2 * m + 1;
        const bool z1 = isF && ((j1 == PAD_TAG) || (j1 == STOP_TAG));
        const int a00 = isF ? (i1 * KK + j0) : (j0 * KK + i1);
        const int a01 = isF ? (i1 * KK + j1) : (j1 * KK + i1);
        const int a10 = isF ? (i2 * KK + j0) : (j0 * KK + i2);
        const int a11 = isF ? (i2 * KK + j1) : (j1 * KK + i2);
        float eA0 = ex2(trans[a00] * LOG2E);
        float eA1 = z1 ? 0.f : ex2(trans[a01] * LOG2E);
        float eB0 = has2 ? ex2(trans[a10] * LOG2E) : 0.f;
        float eB1 = (has2 && !z1) ? ex2(trans[a11] * LOG2E) : 0.f;
        EhA[m] = f2bf2(eA0, eA1);
        EhB[m] = f2bf2(eB0, eB1);
        rs1 += eA0 + eA1;
        rs2 += eB0 + eB1;
    }
    const float ES1 = ex2(trans[STOP_TAG * KK + i1] * LOG2E);
    const float ES2 = has2 ? ex2(trans[STOP_TAG * KK + i2] * LOG2E) : 0.f;

    __nv_bfloat16* pdw = pdh[wid];

    // ---- state (identical to R12) ----
    float p1, p2, padacc, pend = 0.f;
    int c = 0, eprev, escale = 0;
    if (isF) {
        const float base1 = ((i1 == PAD_TAG) ? 0.f : 1.f) + rs1;
        const float base2 = ((has2 && i2 == PAD_TAG) ? 0.f : 1.f) + rs2;
        float em1 = emb[i1];
        float em2 = has2 ? emb[i2] : 0.f;
        p1 = ex2(em1 * LOG2E) * base1;
        p2 = has2 ? (ex2(em2 * LOG2E) * base2) : 0.f;
        padacc = em2;                        // lane 13: i2 == PAD
        pdw[i1] = __float2bfloat16_rn(p1);
        if (has2) pdw[i2] = __float2bfloat16_rn(p2);
        eprev = expof(__shfl_sync(0xffffffffu, p1, 0));
    } else {
        p1 = ES1;                            // beta = w
        p2 = ES2;
        padacc = 0.f;
        float em1 = emb[(size_t)(TT - 1) * KK + i1];
        float em2 = has2 ? emb[(size_t)(TT - 1) * KK + i2] : 0.f;
        pend = em2;
        eprev = expof(__shfl_sync(0xffffffffu, p1, 0));
        const float ne = -(float)eprev;
        pdw[i1] = __float2bfloat16_rn(p1 * ex2(fmaf(em1, LOG2E, ne)));
        if (has2) pdw[i2] = __float2bfloat16_rn(p2 * ex2(fmaf(em2, LOG2E, ne)));
        escale = eprev;
    }
    __syncwarp();

    // ---- bf16 matvec: 6 LDS.128, 48 HFMA2(bf16) in 8 chains,
    //      one bf16 tree level, final combine in fp32 (precision guard)
    auto matvec = [&](float& q1, float& q2) {
        u32 pw[24];
        const uint4* s4 = reinterpret_cast<const uint4*>(pdw);
#pragma unroll
        for (int k = 0; k < 6; ++k) {
            uint4 w = s4[k];
            pw[4 * k]     = w.x;
            pw[4 * k + 1] = w.y;
            pw[4 * k + 2] = w.z;
            pw[4 * k + 3] = w.w;
        }
        u32 a0 = 0u, a1 = 0u, a2 = 0u, a3 = 0u;
        u32 b0 = 0u, b1 = 0u, b2 = 0u, b3 = 0u;
#pragma unroll
        for (int k = 0; k < 24; k += 4) {
            bffma2(a0, EhA[k],     pw[k]);
            bffma2(a1, EhA[k + 1], pw[k + 1]);
            bffma2(a2, EhA[k + 2], pw[k + 2]);
            bffma2(a3, EhA[k + 3], pw[k + 3]);
            bffma2(b0, EhB[k],     pw[k]);
            bffma2(b1, EhB[k + 1], pw[k + 1]);
            bffma2(b2, EhB[k + 2], pw[k + 2]);
            bffma2(b3, EhB[k + 3], pw[k + 3]);
        }
        const u32 sA0 = bfadd2(a0, a1), sA1 = bfadd2(a2, a3);
        const u32 sB0 = bfadd2(b0, b1), sB1 = bfadd2(b2, b3);
        float x0, x1, x2, x3, y0, y1, y2, y3;
        bf2f2(x0, x1, sA0); bf2f2(x2, x3, sA1);
        bf2f2(y0, y1, sB0); bf2f2(y2, y3, sB1);
        q1 = (x0 + x1) + (x2 + x3);
        q2 = (y0 + y1) + (y2 + y3);
    };

    if (isF) {
        // ============ FORWARD: t = 1..511 ============
        auto step = [&](const float* __restrict__ embuf,
                        const float* __restrict__ mkbuf, int tt) {
            const float cem1 = embuf[tt * KK + i1];
            const float cem2 = embuf[tt * KK + i2];
            const float cmk  = mkbuf[tt];
            cfence();
            float q1, q2;
            matvec(q1, q2);
            const bool  m  = (cmk != 0.0f);
            const float ne = -(float)eprev;
            const float g1 = ex2(fmaf(cem1, LOG2E, ne));
            const float g2 = ex2(fmaf(cem2, LOG2E, ne));
            p1 = m ? (q1 * g1) : p1;
            p2 = m ? (q2 * g2) : p2;
            padacc += m ? cem2 : 0.f;
            c      += m ? eprev : 0;
            const float zp = __shfl_sync(0xffffffffu, p1, 0);
            pdw[i1] = __float2bfloat16_rn(p1);
            if (has2) pdw[i2] = __float2bfloat16_rn(p2);
            cfence();
            eprev = expof(zp);
        };
        {   // chunk 0: t = 1..7
            cpwait1();
            __syncwarp();
#pragma unroll 1
            for (int tt = 1; tt < CH; ++tt)
                step(sm_em[wid][0], sm_mk[wid][0], tt);
            issue_chunk(2);
        }
#pragma unroll 1
        for (int cc = 1; cc < FWD_CHUNKS; ++cc) {
            cpwait1();
            __syncwarp();
            const int buf = cc & 1;
#pragma unroll 1
            for (int tt = 0; tt < CH; ++tt)
                step(sm_em[wid][buf], sm_mk[wid][buf], tt);
            if (cc + 2 < FWD_CHUNKS) issue_chunk(cc + 2);
        }
    } else {
        // ============ BACKWARD: t = 1023..512 ============
        auto bstep = [&](const float* __restrict__ embuf,
                         const float* __restrict__ mkbuf, int tt) {
            const float cem1 = embuf[tt * KK + i1];   // em[t-1]
            const float cem2 = embuf[tt * KK + i2];
            const float cmk  = mkbuf[tt];             // mask[t]
            cfence();
            float q1, q2;
            matvec(q1, q2);
            const bool m = (cmk != 0.0f);
            p1 = m ? q1 : p1;
            p2 = m ? q2 : p2;
            padacc += m ? pend : 0.f;
            c      += m ? escale : 0;
            pend = cem2;
            const float zp = __shfl_sync(0xffffffffu, p1, 0);
            const float ne = -(float)eprev;
            const float g1 = ex2(fmaf(cem1, LOG2E, ne));
            const float g2 = ex2(fmaf(cem2, LOG2E, ne));
            pdw[i1] = __float2bfloat16_rn(p1 * g1);
            if (has2) pdw[i2] = __float2bfloat16_rn(p2 * g2);
            cfence();
            escale = eprev;
            eprev = expof(zp);
        };
#pragma unroll 1
        for (int cc = NCHUNK - 1; cc >= FWD_CHUNKS; --cc) {
            cpwait1();
            __syncwarp();
            const int buf = cc & 1;
#pragma unroll 1
            for (int tt = CH - 1; tt >= 0; --tt)
                bstep(sm_em[wid][buf], sm_mk[wid][buf], tt);
            if (cc - 2 >= FWD_CHUNKS) issue_chunk(cc - 2);
        }
    }

    // ---- combine: Z_main = 2^(NEG*log2e + cF + cB) * sum_i alpha_i beta_i
    if (!isF) {
        bd[team][i1] = p1;
        if (has2) bd[team][i2] = p2;
        const float padv = __shfl_sync(0xffffffffu, padacc, 13);
        if (lane == 0) {
            bsc_c[team]   = (float)c;
            bsc_pad[team] = padv;
        }
    }
    __syncthreads();
    if (isF) {
        const float bt1 = bd[team][i1];
        const float bt2 = has2 ? bd[team][i2] : 0.f;
        float s = p1 * bt1 + p2 * bt2;
#pragma unroll
        for (int o = 16; o > 0; o >>= 1)
            s += __shfl_xor_sync(0xffffffffu, s, o);

        const float padF  = __shfl_sync(0xffffffffu, padacc, 13);
        const float Cfull = NEGV * LOG2E + (float)c + bsc_c[team];
        const float main2 = Cfull + lg2(s);
        const float pad2  = (padF + bsc_pad[team] + NEGV) * LOG2E;
        const float hi = fmaxf(main2, pad2);
        const float lo = fminf(main2, pad2);
        const float ans2 = hi + lg2(1.0f + ex2(lo - hi));
        if (lane == 0) out[b] = ans2 * LN2F;
    }
}

extern "C" void kernel_launch(void* const* d_in, const int* in_sizes, int n_in,
                              void* d_out, int out_size) {
    const float* h_tag = (const float*)d_in[0];
    const float* mask  = (const float*)d_in[1];
    const float* trans = (const float*)d_in[2];
    float* out = (float*)d_out;
    (void)in_sizes; (void)n_in; (void)out_size;
    crf_fwd_kernel<<<BB / 4, 256>>>(h_tag, mask, trans, out);
}